// round 3
// baseline (speedup 1.0000x reference)
#include <cuda_runtime.h>
#include <math.h>

#define DEPTHN 2
#define BATCH 4
#define LSEQ 4096
#define DMOD 512
#define DIN 1024
#define DST 16
#define DTRK 32
#define KCONV 4
#define MROWS (BATCH * LSEQ) /* 16384 */

// ---------------- scratch buffers (device globals; no allocation) -------------
__device__ float g_hn[(size_t)MROWS * DMOD];
__device__ float g_xz[(size_t)MROWS * 2 * DIN];
__device__ float g_xq[(size_t)MROWS * DIN];
__device__ float g_dbl[(size_t)MROWS * 64];
__device__ float g_dt[(size_t)MROWS * DIN];
__device__ float g_y[(size_t)MROWS * DIN];
__device__ float g_yg[(size_t)MROWS * DIN];
__device__ float g_h[(size_t)MROWS * DMOD];

// ---------------- layernorm: one block (128 thr) per row of 512 --------------
__global__ __launch_bounds__(128) void ln_kernel(
    const float* __restrict__ x, const float* __restrict__ w,
    const float* __restrict__ b, float* __restrict__ out) {
    int row = blockIdx.x;
    int t = threadIdx.x;
    const float4* xr = (const float4*)(x + (size_t)row * DMOD);
    float4 v = xr[t];
    float s = v.x + v.y + v.z + v.w;
    float sq = v.x * v.x + v.y * v.y + v.z * v.z + v.w * v.w;
#pragma unroll
    for (int o = 16; o; o >>= 1) {
        s += __shfl_xor_sync(0xffffffffu, s, o);
        sq += __shfl_xor_sync(0xffffffffu, sq, o);
    }
    __shared__ float ss[4], sqq[4];
    int wid = t >> 5, lane = t & 31;
    if (lane == 0) { ss[wid] = s; sqq[wid] = sq; }
    __syncthreads();
    s = ss[0] + ss[1] + ss[2] + ss[3];
    sq = sqq[0] + sqq[1] + sqq[2] + sqq[3];
    float mean = s * (1.0f / DMOD);
    float var = sq * (1.0f / DMOD) - mean * mean;
    float inv = rsqrtf(var + 1e-5f);
    float4 w4 = ((const float4*)w)[t];
    float4 b4 = ((const float4*)b)[t];
    float4 o4;
    o4.x = (v.x - mean) * inv * w4.x + b4.x;
    o4.y = (v.y - mean) * inv * w4.y + b4.y;
    o4.z = (v.z - mean) * inv * w4.z + b4.z;
    o4.w = (v.w - mean) * inv * w4.w + b4.w;
    ((float4*)(out + (size_t)row * DMOD))[t] = o4;
}

// ---------------- generic C[M,N] = A[M,K] * B[N,K]^T (NT), fp32 ---------------
// BM=128, BN=64, BK=16, 256 threads, 8x4 per thread.
// EPI: 0 = none, 1 = softplus(acc + bias[n])
__device__ __forceinline__ float softplus_f(float v) {
    return fmaxf(v, 0.0f) + log1pf(__expf(-fabsf(v)));
}

template <int EPI>
__global__ __launch_bounds__(256) void gemm_nt(
    const float* __restrict__ A, int lda,
    const float* __restrict__ B, int ldb,
    float* __restrict__ C, int ldc,
    int K, const float* __restrict__ bias) {
    __shared__ float As[16][132];
    __shared__ float Bs[16][68];
    int m0 = blockIdx.y * 128, n0 = blockIdx.x * 64;
    int tid = threadIdx.x;
    int ar = tid >> 2;           // 0..63
    int ac = (tid & 3) * 4;      // 0,4,8,12
    int ty = tid >> 4, tx = tid & 15;

    float acc[8][4];
#pragma unroll
    for (int i = 0; i < 8; i++)
#pragma unroll
        for (int j = 0; j < 4; j++) acc[i][j] = 0.0f;

    const float* Aptr0 = A + (size_t)(m0 + ar) * lda + ac;
    const float* Aptr1 = A + (size_t)(m0 + ar + 64) * lda + ac;
    const float* Bptr = B + (size_t)(n0 + ar) * ldb + ac;

    for (int k0 = 0; k0 < K; k0 += 16) {
        float4 a0 = *(const float4*)(Aptr0 + k0);
        float4 a1 = *(const float4*)(Aptr1 + k0);
        float4 bb = *(const float4*)(Bptr + k0);
        __syncthreads();
        As[ac + 0][ar] = a0.x; As[ac + 1][ar] = a0.y;
        As[ac + 2][ar] = a0.z; As[ac + 3][ar] = a0.w;
        As[ac + 0][ar + 64] = a1.x; As[ac + 1][ar + 64] = a1.y;
        As[ac + 2][ar + 64] = a1.z; As[ac + 3][ar + 64] = a1.w;
        Bs[ac + 0][ar] = bb.x; Bs[ac + 1][ar] = bb.y;
        Bs[ac + 2][ar] = bb.z; Bs[ac + 3][ar] = bb.w;
        __syncthreads();
#pragma unroll
        for (int k = 0; k < 16; k++) {
            float4 aa0 = *(const float4*)&As[k][ty * 8];
            float4 aa1 = *(const float4*)&As[k][ty * 8 + 4];
            float4 bb4 = *(const float4*)&Bs[k][tx * 4];
            float av[8] = {aa0.x, aa0.y, aa0.z, aa0.w, aa1.x, aa1.y, aa1.z, aa1.w};
            float bv[4] = {bb4.x, bb4.y, bb4.z, bb4.w};
#pragma unroll
            for (int i = 0; i < 8; i++)
#pragma unroll
                for (int j = 0; j < 4; j++) acc[i][j] = fmaf(av[i], bv[j], acc[i][j]);
        }
    }

#pragma unroll
    for (int i = 0; i < 8; i++) {
        int m = m0 + ty * 8 + i;
        int n = n0 + tx * 4;
        float4 o;
        float v0 = acc[i][0], v1 = acc[i][1], v2 = acc[i][2], v3 = acc[i][3];
        if (EPI == 1) {
            v0 = softplus_f(v0 + bias[n + 0]);
            v1 = softplus_f(v1 + bias[n + 1]);
            v2 = softplus_f(v2 + bias[n + 2]);
            v3 = softplus_f(v3 + bias[n + 3]);
        }
        o.x = v0; o.y = v1; o.z = v2; o.w = v3;
        *(float4*)(C + (size_t)m * ldc + n) = o;
    }
}

// ---------------- depthwise causal conv (K=4) + bias + SiLU -------------------
__global__ __launch_bounds__(256) void conv_silu_kernel(
    const float* __restrict__ xz, const float* __restrict__ cw,
    const float* __restrict__ cb, float* __restrict__ xq) {
    int idx = blockIdx.x * 256 + threadIdx.x;   // m*DIN + d
    int d = idx & (DIN - 1);
    int m = idx >> 10;
    int l = m & (LSEQ - 1);
    const float* col = xz + (size_t)m * (2 * DIN) + d;
    float w0 = cw[d * 4 + 0], w1 = cw[d * 4 + 1], w2 = cw[d * 4 + 2], w3 = cw[d * 4 + 3];
    float acc = cb[d];
    if (l >= 3) acc = fmaf(w0, col[-(ptrdiff_t)3 * 2 * DIN], acc);
    if (l >= 2) acc = fmaf(w1, col[-(ptrdiff_t)2 * 2 * DIN], acc);
    if (l >= 1) acc = fmaf(w2, col[-(ptrdiff_t)1 * 2 * DIN], acc);
    acc = fmaf(w3, col[0], acc);
    xq[idx] = acc * (1.0f / (1.0f + __expf(-acc)));   // SiLU
}

// ---------------- selective scan -----------------------------------------------
// block = 256 thr = 16 channels x 16 states; grid = (DIN/16, BATCH)
__global__ __launch_bounds__(256) void scan_kernel(
    const float* __restrict__ dt, const float* __restrict__ xq,
    const float* __restrict__ dbl, const float* __restrict__ A_log,
    float* __restrict__ y) {
    int b = blockIdx.y;
    int d0 = blockIdx.x * 16;
    int tid = threadIdx.x;
    int s = tid & 15, c = tid >> 4;
    int d = d0 + c;
    float a = -__expf(A_log[(size_t)d * DST + s]);
    float h = 0.0f;
    __shared__ float sB[64][16], sC[64][16], sdt[64][16], sx[64][16], sy[64][16];
    size_t base = (size_t)b * LSEQ;
    for (int t0 = 0; t0 < LSEQ; t0 += 64) {
#pragma unroll 4
        for (int i = tid; i < 1024; i += 256) {
            int tt = i >> 4, j = i & 15;
            size_t m = base + t0 + tt;
            sB[tt][j] = dbl[m * 64 + 32 + j];
            sC[tt][j] = dbl[m * 64 + 48 + j];
            sdt[tt][j] = dt[m * DIN + d0 + j];
            sx[tt][j] = xq[m * DIN + d0 + j];
        }
        __syncthreads();
#pragma unroll 4
        for (int t = 0; t < 64; t++) {
            float dtv = sdt[t][c];
            float xv = sx[t][c];
            float dA = __expf(dtv * a);
            h = fmaf(h, dA, dtv * xv * sB[t][s]);
            float p = h * sC[t][s];
            p += __shfl_xor_sync(0xffffffffu, p, 8, 16);
            p += __shfl_xor_sync(0xffffffffu, p, 4, 16);
            p += __shfl_xor_sync(0xffffffffu, p, 2, 16);
            p += __shfl_xor_sync(0xffffffffu, p, 1, 16);
            if (s == 0) sy[t][c] = p;
        }
        __syncthreads();
#pragma unroll 4
        for (int i = tid; i < 1024; i += 256) {
            int tt = i >> 4, j = i & 15;
            y[(base + t0 + tt) * DIN + d0 + j] = sy[tt][j];
        }
        // no extra sync needed: next stage writes sB/sC/sdt/sx (not sy), and all
        // inner-loop reads of those arrays completed before the sync above.
        __syncthreads();
    }
}

// ---------------- gating: yg = (y + xq*D) * silu(z) ---------------------------
__global__ __launch_bounds__(256) void gate_kernel(
    const float* __restrict__ y, const float* __restrict__ xq,
    const float* __restrict__ xz, const float* __restrict__ Dp,
    float* __restrict__ yg) {
    int idx = blockIdx.x * 256 + threadIdx.x;   // m*DIN + d
    int d = idx & (DIN - 1);
    int m = idx >> 10;
    float z = xz[(size_t)m * (2 * DIN) + DIN + d];
    float sz = z * (1.0f / (1.0f + __expf(-z)));
    yg[idx] = (y[idx] + xq[idx] * Dp[d]) * sz;
}

// ------------------------------------------------------------------------------
extern "C" void kernel_launch(void* const* d_in, const int* in_sizes, int n_in,
                              void* d_out, int out_size) {
    const float* x      = (const float*)d_in[0];
    const float* ln_w   = (const float*)d_in[1];
    const float* ln_b   = (const float*)d_in[2];
    const float* in_w   = (const float*)d_in[3];
    const float* conv_w = (const float*)d_in[4];
    const float* conv_b = (const float*)d_in[5];
    const float* xproj_w= (const float*)d_in[6];
    const float* dt_w   = (const float*)d_in[7];
    const float* dt_b   = (const float*)d_in[8];
    const float* A_log  = (const float*)d_in[9];
    const float* Dp     = (const float*)d_in[10];
    const float* out_w  = (const float*)d_in[11];

    float *hn, *xz, *xq, *dbl, *dt, *y, *yg, *hbuf;
    cudaGetSymbolAddress((void**)&hn,  g_hn);
    cudaGetSymbolAddress((void**)&xz,  g_xz);
    cudaGetSymbolAddress((void**)&xq,  g_xq);
    cudaGetSymbolAddress((void**)&dbl, g_dbl);
    cudaGetSymbolAddress((void**)&dt,  g_dt);
    cudaGetSymbolAddress((void**)&y,   g_y);
    cudaGetSymbolAddress((void**)&yg,  g_yg);
    cudaGetSymbolAddress((void**)&hbuf,g_h);

    const float* hin = x;
    for (int i = 0; i < DEPTHN; i++) {
        const float* lw  = ln_w   + (size_t)i * DMOD;
        const float* lb  = ln_b   + (size_t)i * DMOD;
        const float* iw  = in_w   + (size_t)i * 2 * DIN * DMOD;
        const float* cw  = conv_w + (size_t)i * DIN * KCONV;
        const float* cb  = conv_b + (size_t)i * DIN;
        const float* xpw = xproj_w+ (size_t)i * 64 * DIN;
        const float* dtw = dt_w   + (size_t)i * DIN * DTRK;
        const float* dtb = dt_b   + (size_t)i * DIN;
        const float* al  = A_log  + (size_t)i * DIN * DST;
        const float* dpp = Dp     + (size_t)i * DIN;
        const float* ow  = out_w  + (size_t)i * DMOD * DIN;

        ln_kernel<<<MROWS, 128>>>(hin, lw, lb, hn);

        // xz = hn @ in_w^T : M=16384, N=2048, K=512
        gemm_nt<0><<<dim3(2 * DIN / 64, MROWS / 128), 256>>>(
            hn, DMOD, iw, DMOD, xz, 2 * DIN, DMOD, nullptr);

        conv_silu_kernel<<<(size_t)MROWS * DIN / 256, 256>>>(xz, cw, cb, xq);

        // dbl = xq @ xproj_w^T : M=16384, N=64, K=1024
        gemm_nt<0><<<dim3(1, MROWS / 128), 256>>>(
            xq, DIN, xpw, DIN, dbl, 64, DIN, nullptr);

        // dt = softplus(dtr @ dt_w^T + dt_b) : M=16384, N=1024, K=32 (lda=64)
        gemm_nt<1><<<dim3(DIN / 64, MROWS / 128), 256>>>(
            dbl, 64, dtw, DTRK, dt, DIN, DTRK, dtb);

        scan_kernel<<<dim3(DIN / 16, BATCH), 256>>>(dt, xq, dbl, al, y);

        gate_kernel<<<(size_t)MROWS * DIN / 256, 256>>>(y, xq, xz, dpp, yg);

        float* outp = (i == DEPTHN - 1) ? (float*)d_out : hbuf;
        // out = yg @ out_w^T : M=16384, N=512, K=1024
        gemm_nt<0><<<dim3(DMOD / 64, MROWS / 128), 256>>>(
            yg, DIN, ow, DIN, outp, DMOD, DIN, nullptr);

        hin = hbuf;
    }
}

// round 8
// speedup vs baseline: 1.5939x; 1.5939x over previous
#include <cuda_runtime.h>
#include <math.h>

#define DEPTHN 2
#define BATCH 4
#define LSEQ 4096
#define DMOD 512
#define DIN 1024
#define DST 16
#define DTRK 32
#define KCONV 4
#define MROWS (BATCH * LSEQ) /* 16384 */

// ---------------- scratch buffers (device globals; no allocation) -------------
__device__ float g_hn[(size_t)MROWS * DMOD];
__device__ float g_xz[(size_t)MROWS * 2 * DIN];
__device__ float g_xq[(size_t)MROWS * DIN];
__device__ float g_dbl[(size_t)MROWS * 64];
__device__ float g_dt[(size_t)MROWS * DIN];
__device__ float g_y[(size_t)MROWS * DIN];
__device__ float g_yg[(size_t)MROWS * DIN];
__device__ float g_h[(size_t)MROWS * DMOD];

// ---------------- layernorm: one block (128 thr) per row of 512 --------------
__global__ __launch_bounds__(128) void ln_kernel(
    const float* __restrict__ x, const float* __restrict__ w,
    const float* __restrict__ b, float* __restrict__ out) {
    int row = blockIdx.x;
    int t = threadIdx.x;
    const float4* xr = (const float4*)(x + (size_t)row * DMOD);
    float4 v = xr[t];
    float s = v.x + v.y + v.z + v.w;
    float sq = v.x * v.x + v.y * v.y + v.z * v.z + v.w * v.w;
#pragma unroll
    for (int o = 16; o; o >>= 1) {
        s += __shfl_xor_sync(0xffffffffu, s, o);
        sq += __shfl_xor_sync(0xffffffffu, sq, o);
    }
    __shared__ float ss[4], sqq[4];
    int wid = t >> 5, lane = t & 31;
    if (lane == 0) { ss[wid] = s; sqq[wid] = sq; }
    __syncthreads();
    s = ss[0] + ss[1] + ss[2] + ss[3];
    sq = sqq[0] + sqq[1] + sqq[2] + sqq[3];
    float mean = s * (1.0f / DMOD);
    float var = sq * (1.0f / DMOD) - mean * mean;
    float inv = rsqrtf(var + 1e-5f);
    float4 w4 = ((const float4*)w)[t];
    float4 b4 = ((const float4*)b)[t];
    float4 o4;
    o4.x = (v.x - mean) * inv * w4.x + b4.x;
    o4.y = (v.y - mean) * inv * w4.y + b4.y;
    o4.z = (v.z - mean) * inv * w4.z + b4.z;
    o4.w = (v.w - mean) * inv * w4.w + b4.w;
    ((float4*)(out + (size_t)row * DMOD))[t] = o4;
}

// ---------------- tf32 tensor-core GEMM: C[M,N] = A[M,K] * B[N,K]^T ----------
// BN = 64 fixed, BK = 32, 256 threads (8 warps).
// BM = 128: warp grid 4(m) x 2(n), warp tile 32x32  (MT=2 m16-tiles, NT=4 n8-tiles)
// BM = 64 : warp grid 2(m) x 4(n), warp tile 32x16  (MT=2, NT=2)
// EPI: 0 = none, 1 = softplus(acc + bias[n])

__device__ __forceinline__ float softplus_f(float v) {
    return fmaxf(v, 0.0f) + log1pf(__expf(-fabsf(v)));
}

__device__ __forceinline__ float f2tf(float x) {
    unsigned r;
    asm("cvt.rna.tf32.f32 %0, %1;" : "=r"(r) : "f"(x));
    return __uint_as_float(r);
}

__device__ __forceinline__ void mma_tf32(float* d, const unsigned* a, const unsigned* b) {
    asm volatile(
        "mma.sync.aligned.m16n8k8.row.col.f32.tf32.tf32.f32 "
        "{%0,%1,%2,%3}, {%4,%5,%6,%7}, {%8,%9}, {%0,%1,%2,%3};\n"
        : "+f"(d[0]), "+f"(d[1]), "+f"(d[2]), "+f"(d[3])
        : "r"(a[0]), "r"(a[1]), "r"(a[2]), "r"(a[3]), "r"(b[0]), "r"(b[1]));
}

template <int BM, int EPI>
__global__ __launch_bounds__(256) void gemm_tf32(
    const float* __restrict__ A, int lda,
    const float* __restrict__ B, int ldb,
    float* __restrict__ C, int ldc,
    int K, const float* __restrict__ bias) {
    __shared__ float As[BM][36];
    __shared__ float Bs[64][36];

    constexpr int WN = (BM == 128) ? 2 : 4;   // warps along n
    constexpr int NT = (BM == 128) ? 4 : 2;   // n8 tiles per warp
    constexpr int MT = 2;                     // m16 tiles per warp
    constexpr int APASS = BM / 32;

    const int tid = threadIdx.x;
    const int wid = tid >> 5, lane = tid & 31;
    const int gid = lane >> 2, tig = lane & 3;
    const int wm = wid / WN, wn = wid % WN;
    const int m0 = blockIdx.y * BM;
    const int n0 = blockIdx.x * 64;

    float acc[MT][NT][4];
#pragma unroll
    for (int i = 0; i < MT; i++)
#pragma unroll
        for (int j = 0; j < NT; j++)
#pragma unroll
            for (int q = 0; q < 4; q++) acc[i][j][q] = 0.0f;

    // global load mapping: each thread loads float4 at (row = tid/8 + 32p, col = (tid&7)*4)
    const int lr = tid >> 3;
    const int lc = (tid & 7) * 4;
    const float* Ag = A + (size_t)(m0 + lr) * lda + lc;
    const float* Bg = B + (size_t)(n0 + lr) * ldb + lc;

    float4 ar[APASS], br[2];
#pragma unroll
    for (int p = 0; p < APASS; p++) ar[p] = *(const float4*)(Ag + (size_t)p * 32 * lda);
    br[0] = *(const float4*)(Bg);
    br[1] = *(const float4*)(Bg + (size_t)32 * ldb);

    const int kIters = K / 32;
    for (int it = 0; it < kIters; it++) {
        // store staged regs -> smem (tf32-rounded)
#pragma unroll
        for (int p = 0; p < APASS; p++) {
            float4 v = ar[p];
            *(float4*)&As[lr + p * 32][lc] =
                make_float4(f2tf(v.x), f2tf(v.y), f2tf(v.z), f2tf(v.w));
        }
#pragma unroll
        for (int p = 0; p < 2; p++) {
            float4 v = br[p];
            *(float4*)&Bs[lr + p * 32][lc] =
                make_float4(f2tf(v.x), f2tf(v.y), f2tf(v.z), f2tf(v.w));
        }
        __syncthreads();

        if (it + 1 < kIters) {
            int ko = (it + 1) * 32;
#pragma unroll
            for (int p = 0; p < APASS; p++)
                ar[p] = *(const float4*)(Ag + (size_t)p * 32 * lda + ko);
            br[0] = *(const float4*)(Bg + ko);
            br[1] = *(const float4*)(Bg + (size_t)32 * ldb + ko);
        }

#pragma unroll
        for (int ks = 0; ks < 4; ks++) {
            const int k = ks * 8;
            unsigned af[MT][4], bf[NT][2];
#pragma unroll
            for (int mt = 0; mt < MT; mt++) {
                const int mb = wm * 32 + mt * 16;
                af[mt][0] = __float_as_uint(As[mb + gid][k + tig]);
                af[mt][1] = __float_as_uint(As[mb + gid + 8][k + tig]);
                af[mt][2] = __float_as_uint(As[mb + gid][k + tig + 4]);
                af[mt][3] = __float_as_uint(As[mb + gid + 8][k + tig + 4]);
            }
#pragma unroll
            for (int nt = 0; nt < NT; nt++) {
                const int nb = wn * (8 * NT) + nt * 8;
                bf[nt][0] = __float_as_uint(Bs[nb + gid][k + tig]);
                bf[nt][1] = __float_as_uint(Bs[nb + gid][k + tig + 4]);
            }
#pragma unroll
            for (int mt = 0; mt < MT; mt++)
#pragma unroll
                for (int nt = 0; nt < NT; nt++)
                    mma_tf32(acc[mt][nt], af[mt], bf[nt]);
        }
        __syncthreads();
    }

    // epilogue
#pragma unroll
    for (int mt = 0; mt < MT; mt++) {
#pragma unroll
        for (int nt = 0; nt < NT; nt++) {
            int r = m0 + wm * 32 + mt * 16 + gid;
            int c = n0 + wn * (8 * NT) + nt * 8 + 2 * tig;
            float v0 = acc[mt][nt][0], v1 = acc[mt][nt][1];
            float v2 = acc[mt][nt][2], v3 = acc[mt][nt][3];
            if (EPI == 1) {
                float b0 = bias[c], b1 = bias[c + 1];
                v0 = softplus_f(v0 + b0);
                v1 = softplus_f(v1 + b1);
                v2 = softplus_f(v2 + b0);
                v3 = softplus_f(v3 + b1);
            }
            *(float2*)(C + (size_t)r * ldc + c) = make_float2(v0, v1);
            *(float2*)(C + (size_t)(r + 8) * ldc + c) = make_float2(v2, v3);
        }
    }
}

// ---------------- depthwise causal conv (K=4) + bias + SiLU -------------------
__global__ __launch_bounds__(256) void conv_silu_kernel(
    const float* __restrict__ xz, const float* __restrict__ cw,
    const float* __restrict__ cb, float* __restrict__ xq) {
    int idx = blockIdx.x * 256 + threadIdx.x;   // m*DIN + d
    int d = idx & (DIN - 1);
    int m = idx >> 10;
    int l = m & (LSEQ - 1);
    const float* col = xz + (size_t)m * (2 * DIN) + d;
    float w0 = cw[d * 4 + 0], w1 = cw[d * 4 + 1], w2 = cw[d * 4 + 2], w3 = cw[d * 4 + 3];
    float acc = cb[d];
    if (l >= 3) acc = fmaf(w0, col[-(ptrdiff_t)3 * 2 * DIN], acc);
    if (l >= 2) acc = fmaf(w1, col[-(ptrdiff_t)2 * 2 * DIN], acc);
    if (l >= 1) acc = fmaf(w2, col[-(ptrdiff_t)1 * 2 * DIN], acc);
    acc = fmaf(w3, col[0], acc);
    xq[idx] = acc * (1.0f / (1.0f + __expf(-acc)));   // SiLU
}

// ---------------- selective scan -----------------------------------------------
// block = 256 thr = 16 channels x 16 states; grid = (DIN/16, BATCH)
__global__ __launch_bounds__(256) void scan_kernel(
    const float* __restrict__ dt, const float* __restrict__ xq,
    const float* __restrict__ dbl, const float* __restrict__ A_log,
    float* __restrict__ y) {
    int b = blockIdx.y;
    int d0 = blockIdx.x * 16;
    int tid = threadIdx.x;
    int s = tid & 15, c = tid >> 4;
    int d = d0 + c;
    float a = -__expf(A_log[(size_t)d * DST + s]);
    float h = 0.0f;
    __shared__ float sB[64][16], sC[64][16], sdt[64][16], sx[64][16], sy[64][16];
    size_t base = (size_t)b * LSEQ;
    for (int t0 = 0; t0 < LSEQ; t0 += 64) {
#pragma unroll 4
        for (int i = tid; i < 1024; i += 256) {
            int tt = i >> 4, j = i & 15;
            size_t m = base + t0 + tt;
            sB[tt][j] = dbl[m * 64 + 32 + j];
            sC[tt][j] = dbl[m * 64 + 48 + j];
            sdt[tt][j] = dt[m * DIN + d0 + j];
            sx[tt][j] = xq[m * DIN + d0 + j];
        }
        __syncthreads();
#pragma unroll 4
        for (int t = 0; t < 64; t++) {
            float dtv = sdt[t][c];
            float xv = sx[t][c];
            float dA = __expf(dtv * a);
            h = fmaf(h, dA, dtv * xv * sB[t][s]);
            float p = h * sC[t][s];
            p += __shfl_xor_sync(0xffffffffu, p, 8, 16);
            p += __shfl_xor_sync(0xffffffffu, p, 4, 16);
            p += __shfl_xor_sync(0xffffffffu, p, 2, 16);
            p += __shfl_xor_sync(0xffffffffu, p, 1, 16);
            if (s == 0) sy[t][c] = p;
        }
        __syncthreads();
#pragma unroll 4
        for (int i = tid; i < 1024; i += 256) {
            int tt = i >> 4, j = i & 15;
            y[(base + t0 + tt) * DIN + d0 + j] = sy[tt][j];
        }
        __syncthreads();
    }
}

// ---------------- gating: yg = (y + xq*D) * silu(z) ---------------------------
__global__ __launch_bounds__(256) void gate_kernel(
    const float* __restrict__ y, const float* __restrict__ xq,
    const float* __restrict__ xz, const float* __restrict__ Dp,
    float* __restrict__ yg) {
    int idx = blockIdx.x * 256 + threadIdx.x;   // m*DIN + d
    int d = idx & (DIN - 1);
    int m = idx >> 10;
    float z = xz[(size_t)m * (2 * DIN) + DIN + d];
    float sz = z * (1.0f / (1.0f + __expf(-z)));
    yg[idx] = (y[idx] + xq[idx] * Dp[d]) * sz;
}

// ------------------------------------------------------------------------------
extern "C" void kernel_launch(void* const* d_in, const int* in_sizes, int n_in,
                              void* d_out, int out_size) {
    const float* x      = (const float*)d_in[0];
    const float* ln_w   = (const float*)d_in[1];
    const float* ln_b   = (const float*)d_in[2];
    const float* in_w   = (const float*)d_in[3];
    const float* conv_w = (const float*)d_in[4];
    const float* conv_b = (const float*)d_in[5];
    const float* xproj_w= (const float*)d_in[6];
    const float* dt_w   = (const float*)d_in[7];
    const float* dt_b   = (const float*)d_in[8];
    const float* A_log  = (const float*)d_in[9];
    const float* Dp     = (const float*)d_in[10];
    const float* out_w  = (const float*)d_in[11];

    float *hn, *xz, *xq, *dbl, *dt, *y, *yg, *hbuf;
    cudaGetSymbolAddress((void**)&hn,  g_hn);
    cudaGetSymbolAddress((void**)&xz,  g_xz);
    cudaGetSymbolAddress((void**)&xq,  g_xq);
    cudaGetSymbolAddress((void**)&dbl, g_dbl);
    cudaGetSymbolAddress((void**)&dt,  g_dt);
    cudaGetSymbolAddress((void**)&y,   g_y);
    cudaGetSymbolAddress((void**)&yg,  g_yg);
    cudaGetSymbolAddress((void**)&hbuf,g_h);

    const float* hin = x;
    for (int i = 0; i < DEPTHN; i++) {
        const float* lw  = ln_w   + (size_t)i * DMOD;
        const float* lb  = ln_b   + (size_t)i * DMOD;
        const float* iw  = in_w   + (size_t)i * 2 * DIN * DMOD;
        const float* cw  = conv_w + (size_t)i * DIN * KCONV;
        const float* cb  = conv_b + (size_t)i * DIN;
        const float* xpw = xproj_w+ (size_t)i * 64 * DIN;
        const float* dtw = dt_w   + (size_t)i * DIN * DTRK;
        const float* dtb = dt_b   + (size_t)i * DIN;
        const float* al  = A_log  + (size_t)i * DIN * DST;
        const float* dpp = Dp     + (size_t)i * DIN;
        const float* ow  = out_w  + (size_t)i * DMOD * DIN;

        ln_kernel<<<MROWS, 128>>>(hin, lw, lb, hn);

        // xz = hn @ in_w^T : M=16384, N=2048, K=512
        gemm_tf32<128, 0><<<dim3(2 * DIN / 64, MROWS / 128), 256>>>(
            hn, DMOD, iw, DMOD, xz, 2 * DIN, DMOD, nullptr);

        conv_silu_kernel<<<(size_t)MROWS * DIN / 256, 256>>>(xz, cw, cb, xq);

        // dbl = xq @ xproj_w^T : M=16384, N=64, K=1024  (BM=64 -> 256 blocks)
        gemm_tf32<64, 0><<<dim3(1, MROWS / 64), 256>>>(
            xq, DIN, xpw, DIN, dbl, 64, DIN, nullptr);

        // dt = softplus(dtr @ dt_w^T + dt_b) : M=16384, N=1024, K=32 (lda=64)
        gemm_tf32<128, 1><<<dim3(DIN / 64, MROWS / 128), 256>>>(
            dbl, 64, dtw, DTRK, dt, DIN, DTRK, dtb);

        scan_kernel<<<dim3(DIN / 16, BATCH), 256>>>(dt, xq, dbl, al, y);

        gate_kernel<<<(size_t)MROWS * DIN / 256, 256>>>(y, xq, xz, dpp, yg);

        float* outp = (i == DEPTHN - 1) ? (float*)d_out : hbuf;
        // out = yg @ out_w^T : M=16384, N=512, K=1024
        gemm_tf32<128, 0><<<dim3(DMOD / 64, MROWS / 128), 256>>>(
            yg, DIN, ow, DIN, outp, DMOD, DIN, nullptr);

        hin = hbuf;
    }
}